// round 3
// baseline (speedup 1.0000x reference)
#include <cuda_runtime.h>
#include <cuda_bf16.h>
#include <cstdint>

// RandomPooling: y[b,c,h,w] = x[b,c, refl(h+rh[b,h,w]-1), refl(w+rw[b,h,w]-1)]
// B=32, C=3, H=W=512, GAP=1 reflect padding.
// Memory-bound gather: ~268 MB min DRAM traffic.

static constexpr int B = 32;
static constexpr int C = 3;
static constexpr int H = 512;
static constexpr int W = 512;
static constexpr int HW = H * W;          // 262144 = 1<<18
static constexpr int LOG_HW = 18;
static constexpr int LOG_W = 9;

__device__ __forceinline__ int refl(int s, int n) {
    // GAP=1: s in [-1, n]. reflect: -1 -> 1, n -> n-2.
    if (s < 0) s = -s;
    if (s >= n) s = 2 * n - 2 - s;
    return s;
}

__global__ __launch_bounds__(256)
void random_pool_kernel(const float* __restrict__ x,
                        const int*   __restrict__ rh,
                        const int*   __restrict__ rw,
                        float*       __restrict__ out)
{
    // Each thread handles 4 consecutive w-pixels of one (b,h) row.
    int t = blockIdx.x * blockDim.x + threadIdx.x;
    int pix = t << 2;                      // first pixel index (b*HW + h*W + w)
    if (pix >= B * HW) return;

    int b  = pix >> LOG_HW;
    int hw = pix & (HW - 1);
    int h  = hw >> LOG_W;
    int w  = hw & (W - 1);                 // multiple of 4

    // rh/rw are [B,H,W] flat — index loads fully coalesced (int4 per thread)
    int4 rh4 = *reinterpret_cast<const int4*>(rh + pix);
    int4 rw4 = *reinterpret_cast<const int4*>(rw + pix);

    // Source offsets within one channel plane (shared across all 3 channels)
    int sh0 = refl(h + rh4.x - 1, H);
    int sh1 = refl(h + rh4.y - 1, H);
    int sh2 = refl(h + rh4.z - 1, H);
    int sh3 = refl(h + rh4.w - 1, H);

    int sw0 = refl(w + 0 + rw4.x - 1, W);
    int sw1 = refl(w + 1 + rw4.y - 1, W);
    int sw2 = refl(w + 2 + rw4.z - 1, W);
    int sw3 = refl(w + 3 + rw4.w - 1, W);

    int src0 = (sh0 << LOG_W) + sw0;
    int src1 = (sh1 << LOG_W) + sw1;
    int src2 = (sh2 << LOG_W) + sw2;
    int src3 = (sh3 << LOG_W) + sw3;

    // Per-channel gather + vectorized store. All offsets fit in 32 bits
    // (max plane offset = 96*2^18 < 2^25 elements), so keep index math 32-bit.
    unsigned plane = (unsigned)(b * C) << LOG_HW;   // element offset of channel 0 plane
    #pragma unroll
    for (int c = 0; c < C; c++) {
        const float* __restrict__ xc = x + plane;
        float4 v;
        v.x = __ldg(xc + src0);
        v.y = __ldg(xc + src1);
        v.z = __ldg(xc + src2);
        v.w = __ldg(xc + src3);
        *reinterpret_cast<float4*>(out + plane + hw) = v;
        plane += HW;
    }
}

extern "C" void kernel_launch(void* const* d_in, const int* in_sizes, int n_in,
                              void* d_out, int out_size)
{
    const float* x  = (const float*)d_in[0];
    const int*   rh = (const int*)d_in[1];
    const int*   rw = (const int*)d_in[2];
    float*       y  = (float*)d_out;

    const int n_pix = B * HW;              // 8,388,608
    const int threads = 256;
    const int blocks = (n_pix / 4 + threads - 1) / threads;   // 8192
    random_pool_kernel<<<blocks, threads>>>(x, rh, rw, y);
}